// round 5
// baseline (speedup 1.0000x reference)
#include <cuda_runtime.h>

#define ROWS   4096
#define NCOLS  16384
#define NVEC   4096            // float4 blocks per row
#define NPAIRS 8199
#define OUTROW 16398
#define BLOCK  256
#define GROUPS_TOTAL     4100  // group g -> cA(2g),cA(2g+1), cD(2g-1),cD(2g)
#define BLOCKS_X         5
#define GROUPS_PER_BLOCK 820

// Window order: pair m reads x[2m-6+j], tap j pairs with DEC[7-j]
__device__ constexpr float CA_W[8] = {
     0.23037781330885523f,  0.7148465705525415f,   0.6308807679295904f,
    -0.02798376941698385f, -0.18703481171888114f,  0.030841381835986965f,
     0.032883011666982945f, -0.010597401784997278f };
__device__ constexpr float CD_W[8] = {
    -0.010597401784997278f, -0.032883011666982945f, 0.030841381835986965f,
     0.18703481171888114f,  -0.02798376941698385f, -0.6308807679295904f,
     0.7148465705525415f,   -0.23037781330885523f };

__device__ __forceinline__ float4 ld_safe(const float4* __restrict__ p, int j)
{
    if (j >= 0 && j < NVEC) return __ldcg(p + j);
    return make_float4(0.f, 0.f, 0.f, 0.f);
}

__device__ __forceinline__ float4 shfl_up4(float4 v, int d)
{
    float4 r;
    r.x = __shfl_up_sync(0xffffffffu, v.x, d);
    r.y = __shfl_up_sync(0xffffffffu, v.y, d);
    r.z = __shfl_up_sync(0xffffffffu, v.z, d);
    r.w = __shfl_up_sync(0xffffffffu, v.w, d);
    return r;
}

__global__ __launch_bounds__(BLOCK)
void dwt_db4_kernel(const float* __restrict__ x, float* __restrict__ out)
{
    const int row  = blockIdx.y;
    const int g0   = blockIdx.x * GROUPS_PER_BLOCK;
    const int lane = threadIdx.x & 31;
    const float4* __restrict__ xr4 =
        reinterpret_cast<const float4*>(x + (size_t)row * NCOLS);
    float* __restrict__ orow = out + (size_t)row * OUTROW;

    #pragma unroll
    for (int i = 0; i < 4; i++) {
        const int gl = threadIdx.x + i * BLOCK;   // local group index
        const int g  = g0 + gl;                   // global group (may overrun; clamped)

        // main load: one float4 per group, each global byte loaded exactly once
        float4 v   = ld_safe(xr4, g);
        // neighbor float4s via warp shuffle
        float4 vm1 = shfl_up4(v, 1);
        float4 vm2 = shfl_up4(v, 2);
        // halo patch for the two low lanes (cross-warp data; L2 hits)
        if (lane == 0) {
            vm1 = ld_safe(xr4, g - 1);
            vm2 = ld_safe(xr4, g - 2);
        } else if (lane == 1) {
            vm2 = ld_safe(xr4, g - 2);
        }

        if (gl < GROUPS_PER_BLOCK) {
            // 12-float window x[4g-8 .. 4g+3]
            const float wv[12] = { vm2.x, vm2.y, vm2.z, vm2.w,
                                   vm1.x, vm1.y, vm1.z, vm1.w,
                                   v.x,   v.y,   v.z,   v.w };
            float a0 = 0.f, a1 = 0.f, dm = 0.f, d0 = 0.f;
            #pragma unroll
            for (int j = 0; j < 8; j++) {
                a0 = fmaf(CA_W[j], wv[j + 2], a0);   // cA(2g)
                a1 = fmaf(CA_W[j], wv[j + 4], a1);   // cA(2g+1)
                dm = fmaf(CD_W[j], wv[j + 0], dm);   // cD(2g-1)
                d0 = fmaf(CD_W[j], wv[j + 2], d0);   // cD(2g)
            }

            // cA pair {2g, 2g+1} -> float2 at orow[2g]
            if (g < GROUPS_TOTAL - 1) {
                __stcs(reinterpret_cast<float2*>(orow + 2 * g),
                       make_float2(a0, a1));
            } else {                                  // g=4099: only m=8198 exists
                __stcs(orow + 2 * g, a0);
            }
            // cD pair {2g-1, 2g} -> float2 at orow[8198 + 2g]
            if (g > 0) {
                __stcs(reinterpret_cast<float2*>(orow + (NPAIRS - 1) + 2 * g),
                       make_float2(dm, d0));
            } else {                                  // g=0: only cD(0)
                __stcs(orow + NPAIRS, d0);
            }
        }
    }
}

extern "C" void kernel_launch(void* const* d_in, const int* in_sizes, int n_in,
                              void* d_out, int out_size)
{
    const float* x = (const float*)d_in[0];
    float* out = (float*)d_out;
    dim3 grid(BLOCKS_X, ROWS);
    dwt_db4_kernel<<<grid, BLOCK>>>(x, out);
}

// round 8
// speedup vs baseline: 1.0229x; 1.0229x over previous
#include <cuda_runtime.h>

#define ROWS   4096
#define NCOLS  16384
#define NPAIRS 8199
#define OUTROW 16398

#define BLOCK  256

// Quad q (0..2050): computes cA[4q..4q+3] and cD[4q-3..4q]
// from window W[0..19] = x[8q-12 .. 8q+7]  (float4 blocks 2q-3 .. 2q+1)
#define Q_TOTAL         2051
#define QUADS_PER_BLOCK 257
#define BLOCKS_X        8       // 8*257 = 2056 >= 2051
#define SMEM_VEC        517     // float4 blocks 2q0-3 .. 2q0+513
#define SMEM_FLOATS     2068

// Window order: pair m reads x[2m-6+j], tap j pairs with DEC[7-j]
__device__ constexpr float CA_W[8] = {
     0.23037781330885523f,  0.7148465705525415f,   0.6308807679295904f,
    -0.02798376941698385f, -0.18703481171888114f,  0.030841381835986965f,
     0.032883011666982945f, -0.010597401784997278f };
__device__ constexpr float CD_W[8] = {
    -0.010597401784997278f, -0.032883011666982945f, 0.030841381835986965f,
     0.18703481171888114f,  -0.02798376941698385f, -0.6308807679295904f,
     0.7148465705525415f,   -0.23037781330885523f };

__global__ __launch_bounds__(BLOCK)
void dwt_db4_kernel(const float* __restrict__ x, float* __restrict__ out)
{
    __shared__ float s[SMEM_FLOATS];

    const int row  = blockIdx.y;
    const int q0   = blockIdx.x * QUADS_PER_BLOCK;
    const int base = 8 * q0 - 12;                 // x float index of s[0]; %4 == 0
    const float* __restrict__ xr = x + (size_t)row * NCOLS;

    // ---- stage tile (each global float loaded exactly once, L1 bypassed) ----
    if (blockIdx.x != 0 && blockIdx.x != BLOCKS_X - 1) {
        #pragma unroll
        for (int i = 0; i < 3; i++) {
            const int j = threadIdx.x + i * BLOCK;
            if (j < SMEM_VEC) {
                float4 v = __ldcg(reinterpret_cast<const float4*>(xr + base + 4 * j));
                *reinterpret_cast<float4*>(s + 4 * j) = v;
            }
        }
    } else {
        #pragma unroll
        for (int i = 0; i < 3; i++) {
            const int j = threadIdx.x + i * BLOCK;
            if (j < SMEM_VEC) {
                const int gi = base + 4 * j;
                float4 v;
                if (gi >= 0 && gi + 3 < NCOLS) {
                    v = __ldcg(reinterpret_cast<const float4*>(xr + gi));
                } else {
                    v.x = (gi + 0 >= 0 && gi + 0 < NCOLS) ? xr[gi + 0] : 0.0f;
                    v.y = (gi + 1 >= 0 && gi + 1 < NCOLS) ? xr[gi + 1] : 0.0f;
                    v.z = (gi + 2 >= 0 && gi + 2 < NCOLS) ? xr[gi + 2] : 0.0f;
                    v.w = (gi + 3 >= 0 && gi + 3 < NCOLS) ? xr[gi + 3] : 0.0f;
                }
                *reinterpret_cast<float4*>(s + 4 * j) = v;
            }
        }
    }
    __syncthreads();

    float* __restrict__ orow = out + (size_t)row * OUTROW;
    // orow alignment: row*16398 % 4 == 2*(row&1)  -> 16B-aligned only for even rows
    const bool row16 = ((row & 1) == 0);

    #pragma unroll
    for (int i = 0; i < 2; i++) {
        const int ql = threadIdx.x + i * BLOCK;
        if (ql < QUADS_PER_BLOCK) {
            const int q = q0 + ql;
            if (q < Q_TOTAL) {
                // 20-float window via 5 conflict-free LDS.128 (32B-aligned base)
                const float* wp = s + 8 * ql;
                const float4 v0 = *reinterpret_cast<const float4*>(wp + 0);
                const float4 v1 = *reinterpret_cast<const float4*>(wp + 4);
                const float4 v2 = *reinterpret_cast<const float4*>(wp + 8);
                const float4 v3 = *reinterpret_cast<const float4*>(wp + 12);
                const float4 v4 = *reinterpret_cast<const float4*>(wp + 16);
                const float W[20] = { v0.x, v0.y, v0.z, v0.w,
                                      v1.x, v1.y, v1.z, v1.w,
                                      v2.x, v2.y, v2.z, v2.w,
                                      v3.x, v3.y, v3.z, v3.w,
                                      v4.x, v4.y, v4.z, v4.w };

                float d0 = 0.f, d1 = 0.f, d2 = 0.f, d3 = 0.f;
                float a0 = 0.f, a1 = 0.f, a2 = 0.f, a3 = 0.f;
                #pragma unroll
                for (int j = 0; j < 8; j++) {
                    d0 = fmaf(CD_W[j], W[j +  0], d0);   // cD(4q-3)
                    d1 = fmaf(CD_W[j], W[j +  2], d1);   // cD(4q-2)
                    d2 = fmaf(CD_W[j], W[j +  4], d2);   // cD(4q-1)
                    d3 = fmaf(CD_W[j], W[j +  6], d3);   // cD(4q)
                    a0 = fmaf(CA_W[j], W[j +  6], a0);   // cA(4q)
                    a1 = fmaf(CA_W[j], W[j +  8], a1);   // cA(4q+1)
                    a2 = fmaf(CA_W[j], W[j + 10], a2);   // cA(4q+2)
                    a3 = fmaf(CA_W[j], W[j + 12], a3);   // cA(4q+3)
                }

                // ---- cA: orow[4q .. 4q+3] ----
                if (q <= 2048) {
                    float* p = orow + 4 * q;
                    if (row16) {
                        __stcs(reinterpret_cast<float4*>(p),
                               make_float4(a0, a1, a2, a3));
                    } else {
                        __stcs(reinterpret_cast<float2*>(p),     make_float2(a0, a1));
                        __stcs(reinterpret_cast<float2*>(p + 2), make_float2(a2, a3));
                    }
                } else if (q == 2049) {              // cA 8196..8198 only
                    __stcs(reinterpret_cast<float2*>(orow + 8196),
                           make_float2(a0, a1));
                    __stcs(orow + 8198, a2);
                }                                    // q==2050: no cA

                // ---- cD: orow[8196+4q .. 8199+4q] ----
                if (q >= 1 && q <= 2049) {
                    float* p = orow + 8196 + 4 * q;
                    if (row16) {
                        __stcs(reinterpret_cast<float4*>(p),
                               make_float4(d0, d1, d2, d3));
                    } else {
                        __stcs(reinterpret_cast<float2*>(p),     make_float2(d0, d1));
                        __stcs(reinterpret_cast<float2*>(p + 2), make_float2(d2, d3));
                    }
                } else if (q == 0) {                 // only cD(0)
                    __stcs(orow + 8199, d3);
                } else {                             // q==2050: cD 8197, 8198
                    __stcs(reinterpret_cast<float2*>(orow + 16396),
                           make_float2(d0, d1));
                }
            }
        }
    }
}

extern "C" void kernel_launch(void* const* d_in, const int* in_sizes, int n_in,
                              void* d_out, int out_size)
{
    const float* x = (const float*)d_in[0];
    float* out = (float*)d_out;
    dim3 grid(BLOCKS_X, ROWS);
    dwt_db4_kernel<<<grid, BLOCK>>>(x, out);
}

// round 9
// speedup vs baseline: 1.1250x; 1.0999x over previous
#include <cuda_runtime.h>

#define ROWS   4096
#define NCOLS  16384
#define NVEC   4096            // float4 blocks per row
#define NPAIRS 8199
#define OUTROW 16398
#define BLOCK  256
#define GROUPS_TOTAL     4100  // group g -> cA(2g),cA(2g+1), cD(2g-1),cD(2g)
#define BLOCKS_X         5
#define GROUPS_PER_BLOCK 820   // 5*820 = 4100 exactly

// Window order: pair m reads x[2m-6+j], tap j pairs with DEC[7-j]
__device__ constexpr float CA_W[8] = {
     0.23037781330885523f,  0.7148465705525415f,   0.6308807679295904f,
    -0.02798376941698385f, -0.18703481171888114f,  0.030841381835986965f,
     0.032883011666982945f, -0.010597401784997278f };
__device__ constexpr float CD_W[8] = {
    -0.010597401784997278f, -0.032883011666982945f, 0.030841381835986965f,
     0.18703481171888114f,  -0.02798376941698385f, -0.6308807679295904f,
     0.7148465705525415f,   -0.23037781330885523f };

__device__ __forceinline__ float4 ldz(const float4* __restrict__ p, int j)
{
    if (j >= 0 && j < NVEC) return p[j];
    return make_float4(0.f, 0.f, 0.f, 0.f);
}

__global__ __launch_bounds__(BLOCK)
void dwt_db4_kernel(const float* __restrict__ x, float* __restrict__ out)
{
    const int row = blockIdx.y;
    const int g0  = blockIdx.x * GROUPS_PER_BLOCK;
    const float4* __restrict__ xr4 =
        reinterpret_cast<const float4*>(x + (size_t)row * NCOLS);
    float* __restrict__ orow = out + (size_t)row * OUTROW;

    // only edge blocks can touch out-of-range float4 indices (block-uniform)
    const bool edge = (blockIdx.x == 0) || (blockIdx.x == BLOCKS_X - 1);

    #pragma unroll
    for (int i = 0; i < 4; i++) {
        const int gl = threadIdx.x + i * BLOCK;      // 820 = 3*256 + 52
        if (gl < GROUPS_PER_BLOCK) {
            const int g = g0 + gl;

            // 12-float window x[4g-8 .. 4g+3] = float4 blocks g-2, g-1, g.
            // Consecutive lanes are 16B apart per load -> fully coalesced;
            // overlap between the three loads is served by L1 hits.
            float4 v0, v1, v2;
            if (edge) {
                v0 = ldz(xr4, g - 2);
                v1 = ldz(xr4, g - 1);
                v2 = ldz(xr4, g);
            } else {
                v0 = xr4[g - 2];
                v1 = xr4[g - 1];
                v2 = xr4[g];
            }

            const float wv[12] = { v0.x, v0.y, v0.z, v0.w,
                                   v1.x, v1.y, v1.z, v1.w,
                                   v2.x, v2.y, v2.z, v2.w };

            float a0 = 0.f, a1 = 0.f, dm = 0.f, d0 = 0.f;
            #pragma unroll
            for (int j = 0; j < 8; j++) {
                a0 = fmaf(CA_W[j], wv[j + 2], a0);   // cA(2g)
                a1 = fmaf(CA_W[j], wv[j + 4], a1);   // cA(2g+1)
                dm = fmaf(CD_W[j], wv[j + 0], dm);   // cD(2g-1)
                d0 = fmaf(CD_W[j], wv[j + 2], d0);   // cD(2g)
            }

            // cA pair {2g, 2g+1} at orow[2g] (8B aligned for every row)
            if (g < GROUPS_TOTAL - 1) {
                __stcs(reinterpret_cast<float2*>(orow + 2 * g),
                       make_float2(a0, a1));
            } else {                                  // g=4099: only m=8198 exists
                __stcs(orow + 2 * g, a0);
            }
            // cD pair {2g-1, 2g} at orow[8198 + 2g] (8B aligned)
            if (g > 0) {
                __stcs(reinterpret_cast<float2*>(orow + (NPAIRS - 1) + 2 * g),
                       make_float2(dm, d0));
            } else {                                  // g=0: only cD(0)
                __stcs(orow + NPAIRS, d0);
            }
        }
    }
}

extern "C" void kernel_launch(void* const* d_in, const int* in_sizes, int n_in,
                              void* d_out, int out_size)
{
    const float* x = (const float*)d_in[0];
    float* out = (float*)d_out;
    dim3 grid(BLOCKS_X, ROWS);
    dwt_db4_kernel<<<grid, BLOCK>>>(x, out);
}

// round 11
// speedup vs baseline: 1.2290x; 1.0924x over previous
#include <cuda_runtime.h>

#define ROWS   4096
#define NCOLS  16384
#define NVEC   4096            // float4 blocks per row
#define NPAIRS 8199
#define OUTROW 16398
#define BLOCK  256
#define GROUPS_TOTAL 4100      // group g -> cA(2g),cA(2g+1), cD(2g-1),cD(2g)
#define BLOCKS_X     4
#define GPB          1024      // unguarded groups per block; tail 4096..4099 on block 3

// Window order: pair m reads x[2m-6+j], tap j pairs with DEC[7-j]
__device__ constexpr float CA_W[8] = {
     0.23037781330885523f,  0.7148465705525415f,   0.6308807679295904f,
    -0.02798376941698385f, -0.18703481171888114f,  0.030841381835986965f,
     0.032883011666982945f, -0.010597401784997278f };
__device__ constexpr float CD_W[8] = {
    -0.010597401784997278f, -0.032883011666982945f, 0.030841381835986965f,
     0.18703481171888114f,  -0.02798376941698385f, -0.6308807679295904f,
     0.7148465705525415f,   -0.23037781330885523f };

__device__ __forceinline__ float4 ldz(const float4* __restrict__ p, int j)
{
    if (j >= 0 && j < NVEC) return p[j];
    return make_float4(0.f, 0.f, 0.f, 0.f);
}

__global__ __launch_bounds__(BLOCK, 3)
void dwt_db4_kernel(const float* __restrict__ x, float* __restrict__ out)
{
    const int row = blockIdx.y;
    const int bx  = blockIdx.x;
    const int gb  = bx * GPB + threadIdx.x;          // first group of this thread
    const float4* __restrict__ xr4 =
        reinterpret_cast<const float4*>(x + (size_t)row * NCOLS);
    float* __restrict__ orow = out + (size_t)row * OUTROW;

    // ---- front-batched loads: 12 independent LDG.128 per thread ----
    float4 w0[4], w1[4], w2[4];
    if (bx == 0) {
        #pragma unroll
        for (int i = 0; i < 4; i++) {
            const int g = gb + i * BLOCK;
            w0[i] = ldz(xr4, g - 2);
            w1[i] = ldz(xr4, g - 1);
            w2[i] = ldz(xr4, g);
        }
    } else {
        #pragma unroll
        for (int i = 0; i < 4; i++) {
            const int g = gb + i * BLOCK;            // g <= 4095 -> all in range
            w0[i] = xr4[g - 2];
            w1[i] = xr4[g - 1];
            w2[i] = xr4[g];
        }
    }

    // ---- compute + store ----
    #pragma unroll
    for (int i = 0; i < 4; i++) {
        const int g = gb + i * BLOCK;
        const float wv[12] = { w0[i].x, w0[i].y, w0[i].z, w0[i].w,
                               w1[i].x, w1[i].y, w1[i].z, w1[i].w,
                               w2[i].x, w2[i].y, w2[i].z, w2[i].w };
        float a0 = 0.f, a1 = 0.f, dm = 0.f, d0 = 0.f;
        #pragma unroll
        for (int j = 0; j < 8; j++) {
            a0 = fmaf(CA_W[j], wv[j + 2], a0);   // cA(2g)
            a1 = fmaf(CA_W[j], wv[j + 4], a1);   // cA(2g+1)
            dm = fmaf(CD_W[j], wv[j + 0], dm);   // cD(2g-1)
            d0 = fmaf(CD_W[j], wv[j + 2], d0);   // cD(2g)
        }
        // g <= 4095 here: cA pair always full, cD pair full unless g==0
        __stcs(reinterpret_cast<float2*>(orow + 2 * g), make_float2(a0, a1));
        if (bx != 0 || i != 0 || threadIdx.x != 0) {
            __stcs(reinterpret_cast<float2*>(orow + (NPAIRS - 1) + 2 * g),
                   make_float2(dm, d0));
        } else {
            __stcs(orow + NPAIRS, d0);           // g==0: only cD(0)
        }
    }

    // ---- tail groups 4096..4099 (block 3, 4 threads) ----
    if (bx == BLOCKS_X - 1 && threadIdx.x < GROUPS_TOTAL - BLOCKS_X * GPB) {
        const int g = BLOCKS_X * GPB + threadIdx.x;  // 4096..4099
        const float4 t0 = ldz(xr4, g - 2);
        const float4 t1 = ldz(xr4, g - 1);
        const float4 t2 = ldz(xr4, g);
        const float wv[12] = { t0.x, t0.y, t0.z, t0.w,
                               t1.x, t1.y, t1.z, t1.w,
                               t2.x, t2.y, t2.z, t2.w };
        float a0 = 0.f, a1 = 0.f, dm = 0.f, d0 = 0.f;
        #pragma unroll
        for (int j = 0; j < 8; j++) {
            a0 = fmaf(CA_W[j], wv[j + 2], a0);
            a1 = fmaf(CA_W[j], wv[j + 4], a1);
            dm = fmaf(CD_W[j], wv[j + 0], dm);
            d0 = fmaf(CD_W[j], wv[j + 2], d0);
        }
        if (g < GROUPS_TOTAL - 1) {
            __stcs(reinterpret_cast<float2*>(orow + 2 * g), make_float2(a0, a1));
        } else {
            __stcs(orow + 2 * g, a0);                 // g=4099: only m=8198
        }
        __stcs(reinterpret_cast<float2*>(orow + (NPAIRS - 1) + 2 * g),
               make_float2(dm, d0));                  // g>=1 always
    }
}

extern "C" void kernel_launch(void* const* d_in, const int* in_sizes, int n_in,
                              void* d_out, int out_size)
{
    const float* x = (const float*)d_in[0];
    float* out = (float*)d_out;
    dim3 grid(BLOCKS_X, ROWS);
    dwt_db4_kernel<<<grid, BLOCK>>>(x, out);
}